// round 10
// baseline (speedup 1.0000x reference)
#include <cuda_runtime.h>
#include <cuda_fp16.h>
#include <cstdint>

#define Bn 4
#define Nn 256
#define Cc 32
#define Mm 4
#define OUTn 64

// ---------------- scratch (device globals: no allocation allowed) ----------------
__device__ float g_S1 [Bn*Nn*Cc];     // rowsum mean: S1[b,t,c] = (1/n) sum_i x[b,i,t,c]
__device__ float g_S1p[Bn*32*Nn*Cc];  // S1 strip partials (32 strips of 8 i's)
__device__ float g_S2 [Bn*Nn*Cc];     // colsum mean: S2[b,t,c] = (1/n) sum_j x[b,t,j,c]
__device__ float g_D  [Bn*Nn*Cc];     // diag
__device__ float g_p  [Bn*Nn*Mm];     // sigmoid neighborhood
__device__ float g_U  [Bn*Nn*Mm*Cc];  // U[b,t,m,c] = (1/n) sum_i p[i,m] x[b,i,t,c]
__device__ float g_V  [Bn*Nn*Mm*Cc];  // V[b,t,m,c] = (1/n) sum_j p[j,m] x[b,t,j,c]
__device__ float g_pV [Bn*128*Nn];    // pV[b][m*32+c][t] = p[t,m]*V[t,m,c]  (t contiguous)
__device__ float g_ds2[Bn*128];       // (1/n) sum_t p^2 D
__device__ float g_add[Bn*Nn*OUTn];   // per (b, j, o) additive term
__device__ __half g_Wt[OUTn*2*Mm*Cc]; // w2d transposed: Wt[o][k]

// ---------------- sweep 1: strip blocks (S2 full + S1 partials) + w2d->half ----------------
__global__ void k_sweep1(const float* __restrict__ x, const float* __restrict__ w2d){
    int blk = blockIdx.x;
    int tid = threadIdx.x;
    if (blk >= Bn*32){
        int idx = (blk - Bn*32) * 256 + tid;   // 16384
        int o = idx >> 8, k = idx & 255;
        g_Wt[idx] = __float2half(w2d[k*OUTn + o]);
        return;
    }
    int b = blk >> 5, s = blk & 31, i0 = s*8;
    int c = tid & 31, g = tid >> 5;
    const float* xb = x + (size_t)(b*Nn + i0)*Nn*Cc;
    float s1acc[32];
    #pragma unroll
    for (int jj = 0; jj < 32; jj++) s1acc[jj] = 0.f;
    float s2acc[8];
    #pragma unroll 2
    for (int i = 0; i < 8; i++){
        const float* xr = xb + (size_t)i*Nn*Cc + g*Cc + c;
        float ss = 0.f;
        #pragma unroll
        for (int jj = 0; jj < 32; jj++){
            float v = xr[jj*8*Cc];
            s1acc[jj] += v; ss += v;
        }
        s2acc[i] = ss;
    }
    __shared__ float red[8][8][32];
    #pragma unroll
    for (int i = 0; i < 8; i++) red[g][i][c] = s2acc[i];
    {   // S1 strip-partial write: thread owns (j = g+8*jj, c)
        float* dst = g_S1p + ((size_t)(b*32 + s)*Nn)*Cc + c;
        #pragma unroll
        for (int jj = 0; jj < 32; jj++) dst[(g + jj*8)*Cc] = s1acc[jj];
    }
    __syncthreads();
    {   // S2 reduce: 8 i x 32 c
        int ii = tid >> 5, cc = tid & 31;
        float tot = 0.f;
        #pragma unroll
        for (int k = 0; k < 8; k++) tot += red[k][ii][cc];
        g_S2[(b*Nn + i0 + ii)*Cc + cc] = tot * (1.0f/Nn);
    }
}

// ---------------- neighborhood: S1 reduce + D grab + p + ds2, 1024 threads ----------------
__global__ __launch_bounds__(1024) void k_neighb(const float* __restrict__ x,
                         const float* __restrict__ w1, const float* __restrict__ b1,
                         const float* __restrict__ w0, const float* __restrict__ b0){
    int b = blockIdx.x;
    __shared__ float w1s[3*Cc*Mm];   // 384
    __shared__ float w0s[2*Cc*Mm];   // 256
    __shared__ float rcs[Cc], ds[Cc], z0[Mm];
    __shared__ float r1[32][32], r2[32][32];
    int tid = threadIdx.x;
    if (tid < 3*Cc*Mm) w1s[tid] = w1[tid];
    if (tid < 2*Cc*Mm) w0s[tid] = w0[tid];

    // pre-phase: reduce S1 partials (float4) + grab diagonal
    #pragma unroll
    for (int q = 0; q < 2; q++){
        int o4 = tid + q*1024;           // float4 index in [256 t][8 c4]
        float4 acc = make_float4(0.f,0.f,0.f,0.f);
        #pragma unroll
        for (int s = 0; s < 32; s++){
            float4 v = ((const float4*)g_S1p)[(size_t)(b*32 + s)*2048 + o4];
            acc.x += v.x; acc.y += v.y; acc.z += v.z; acc.w += v.w;
        }
        ((float4*)g_S1)[b*2048 + o4] = make_float4(acc.x*(1.0f/Nn), acc.y*(1.0f/Nn),
                                                   acc.z*(1.0f/Nn), acc.w*(1.0f/Nn));
        int t = o4 >> 3, c4 = o4 & 7;
        float4 dv = *(const float4*)(x + ((size_t)(b*Nn + t)*Nn + t)*Cc + c4*4);
        ((float4*)g_D)[b*2048 + o4] = dv;
    }
    __syncthreads();

    int c = tid & 31, g = tid >> 5;     // 32 groups
    float s1 = 0.f, s2 = 0.f;
    #pragma unroll
    for (int t = g; t < Nn; t += 32){
        s1 += g_S1[(b*Nn + t)*Cc + c];
        s2 += g_D [(b*Nn + t)*Cc + c];
    }
    r1[g][c] = s1; r2[g][c] = s2;
    __syncthreads();
    if (tid < 32){
        float a = 0.f, d = 0.f;
        #pragma unroll
        for (int k = 0; k < 32; k++){ a += r1[k][c]; d += r2[k][c]; }
        rcs[c] = a * (1.0f/Nn);
        ds[c]  = d * (1.0f/Nn);
    }
    __syncthreads();
    if (tid < Mm){
        int m = tid;
        float z = b0[m];
        #pragma unroll
        for (int cc = 0; cc < Cc; cc++)
            z += rcs[cc]*w0s[cc*Mm + m] + ds[cc]*w0s[(Cc+cc)*Mm + m];
        z0[m] = z;
    }
    __syncthreads();
    {
        int t = tid >> 2, m = tid & 3;
        const float* S1r = &g_S1[(b*Nn + t)*Cc];
        const float* S2r = &g_S2[(b*Nn + t)*Cc];
        const float* Dr  = &g_D [(b*Nn + t)*Cc];
        float node = b1[m] + z0[m];
        #pragma unroll
        for (int cc = 0; cc < Cc; cc++)
            node += S1r[cc]*w1s[cc*Mm+m] + S2r[cc]*w1s[(Cc+cc)*Mm+m] + Dr[cc]*w1s[(2*Cc+cc)*Mm+m];
        g_p[(b*Nn + t)*Mm + m] = 1.0f / (1.0f + expf(-node));
    }
    __syncthreads();   // p visible block-wide

    // tail: ds2[m,c] = (1/n) sum_t p[t,m]^2 D[t,c]
    {
        int mc = tid & 127, slice = tid >> 7;
        int m = mc >> 5, cc = mc & 31;
        float s = 0.f;
        int t0 = slice*32;
        #pragma unroll 8
        for (int t = t0; t < t0+32; t++){
            float pv = g_p[(b*Nn + t)*Mm + m];
            s += pv * pv * g_D[(b*Nn + t)*Cc + cc];
        }
        ((float*)r1)[tid] = s;
        __syncthreads();
        if (tid < 128){
            float tot = 0.f;
            #pragma unroll
            for (int k = 0; k < 8; k++) tot += ((float*)r1)[k*128 + tid];
            g_ds2[b*128 + tid] = tot * (1.0f/Nn);
        }
    }
}

// ---------------- sweep 2: V and U; V-blocks also emit pV ----------------
__global__ void k_sweep2(const float* __restrict__ x){
    int blk = blockIdx.x;
    bool is_v = blk < Bn*Nn;
    int bt = is_v ? blk : blk - Bn*Nn;
    int b = bt >> 8, t = bt & (Nn-1);
    const float* base;
    size_t stride;
    if (is_v){ base = x + (size_t)bt * Nn * Cc;                     stride = Cc; }
    else     { base = x + (size_t)b*Nn*Nn*Cc + (size_t)t*Cc;        stride = (size_t)Nn*Cc; }
    __shared__ float pv[Nn*Mm];
    __shared__ float red[8*Mm*32];
    int tid = threadIdx.x;
    for (int idx = tid; idx < Nn*Mm; idx += 256) pv[idx] = g_p[b*Nn*Mm + idx];
    __syncthreads();
    int c = tid & 31, g = tid >> 5;
    float acc[Mm] = {0.f,0.f,0.f,0.f};
    #pragma unroll 8
    for (int j = g; j < Nn; j += 8){
        float v = base[(size_t)j*stride + c];
        #pragma unroll
        for (int m = 0; m < Mm; m++) acc[m] += v * pv[j*Mm + m];
    }
    #pragma unroll
    for (int m = 0; m < Mm; m++) red[(g*Mm + m)*32 + c] = acc[m];
    __syncthreads();
    if (g < Mm){
        int m = g;
        float s = 0.f;
        #pragma unroll
        for (int k = 0; k < 8; k++) s += red[(k*Mm + m)*32 + c];
        float val = s * (1.0f/Nn);
        if (is_v){
            g_V[(bt*Mm + m)*Cc + c] = val;
            float pt = pv[t*Mm + m];
            g_pV[((size_t)b*128 + m*32 + c)*Nn + t] = pt * val;
        } else {
            g_U[(bt*Mm + m)*Cc + c] = val;
        }
    }
}

// ---------------- add[b,t,o]: 256 blocks, prologue does rcs2 (from pV) + z0 ----------------
#define ADD_SMEM (4*384*4 + 96*64*4)
__global__ void k_add(const float* __restrict__ w1d, const float* __restrict__ w0d,
                      const float* __restrict__ b0d, const float* __restrict__ b1d,
                      const float* __restrict__ b2d){
    extern __shared__ float ash[];
    float* o1  = ash;            // [4][384]
    float* wsh = ash + 4*384;    // [96][64] chunk of w1d
    __shared__ float pr1[256];
    __shared__ float rsh[128], dsh[128], zred[256], z0sh[64];
    int b = blockIdx.x >> 6;
    int t0 = (blockIdx.x & 63) * 4;
    int tid = threadIdx.x;

    // rcs2 partial: thread (mc, half) reduces 128 contiguous pV values (32 float4)
    {
        int mc = tid & 127, half = tid >> 7;
        const float4* p4 = (const float4*)(g_pV + ((size_t)b*128 + mc)*Nn + half*128);
        float s = 0.f;
        #pragma unroll
        for (int k = 0; k < 32; k++){
            float4 v = p4[k];
            s += v.x + v.y + v.z + v.w;
        }
        pr1[tid] = s;
    }
    // fill o1 for 4 t's: 1536 elements
    #pragma unroll
    for (int it = 0; it < 6; it++){
        int idx = tid + it*256;
        int tl = idx / 384, k = idx - tl*384;
        int t = t0 + tl;
        int seg = k >> 7, mc = k & 127;
        int m = mc >> 5, c = mc & 31;
        float pv = g_p[(b*Nn + t)*Mm + m];
        float val;
        if (seg == 0)      val = pv * g_U[((b*Nn + t)*Mm + m)*Cc + c];
        else if (seg == 1) val = pv * g_V[((b*Nn + t)*Mm + m)*Cc + c];
        else               val = pv * pv * g_D[(b*Nn + t)*Cc + c];
        o1[idx] = val;
    }
    __syncthreads();
    if (tid < 128){
        rsh[tid] = (pr1[tid] + pr1[tid+128]) * (1.0f/Nn);
        dsh[tid] = g_ds2[b*128 + tid];
    }
    __syncthreads();
    {
        int o = tid & 63, q = tid >> 6;
        float s = 0.f;
        int k0 = q*32;
        #pragma unroll
        for (int k = k0; k < k0+32; k++)
            s += rsh[k]*w0d[k*OUTn + o] + dsh[k]*w0d[(128+k)*OUTn + o];
        zred[tid] = s;
    }
    __syncthreads();
    if (tid < 64)
        z0sh[tid] = zred[tid] + zred[tid+64] + zred[tid+128] + zred[tid+192]
                  + b0d[tid] + b1d[tid] + b2d[tid];

    int tq = tid >> 6, o = tid & 63;
    float acc = 0.f;
    #pragma unroll
    for (int chunk = 0; chunk < 4; chunk++){
        __syncthreads();
        {   // stage 96 rows of w1d: 1536 float4
            const float4* w4 = (const float4*)(w1d + chunk*96*64);
            #pragma unroll
            for (int it = 0; it < 6; it++)
                ((float4*)wsh)[tid + it*256] = w4[tid + it*256];
        }
        __syncthreads();
        #pragma unroll 8
        for (int k = 0; k < 96; k++)
            acc += o1[tq*384 + chunk*96 + k] * wsh[k*64 + o];
    }
    g_add[(b*Nn + t0 + tq)*OUTn + o] = acc + z0sh[o];
}

// ---------------- main fused GEMM: JPB 4, column-tile register prefetch ----------------
__device__ __forceinline__ void mma16816(float* c, const uint32_t* a, uint32_t b0, uint32_t b1){
    asm volatile("mma.sync.aligned.m16n8k16.row.col.f32.f16.f16.f32 "
        "{%0,%1,%2,%3}, {%4,%5,%6,%7}, {%8,%9}, {%0,%1,%2,%3};\n"
        : "+f"(c[0]), "+f"(c[1]), "+f"(c[2]), "+f"(c[3])
        : "r"(a[0]), "r"(a[1]), "r"(a[2]), "r"(a[3]), "r"(b0), "r"(b1));
}

#define AS 264
#define SMEM_MAIN (128*AS*2 + 64*AS*2 + 512*4 + 64*4)
#define JPB 4

__global__ __launch_bounds__(256, 2) void k_main(const float* __restrict__ x, float* __restrict__ out){
    extern __shared__ __align__(16) char smem[];
    __half* Ash  = (__half*)smem;                 // [128][AS]
    __half* Wsh  = Ash + 128*AS;                  // [64][AS]
    float*  sshf = (float*)(Wsh + 64*AS);         // [128][4] pi factors
    float*  addsh = sshf + 512;                   // [64]

    int blk = blockIdx.x;
    int ib = blk & 1, jp = (blk >> 1) & 63, b = blk >> 7;
    int i0 = ib * 128;
    int tid = threadIdx.x;

    {
        const uint4* Wt4 = (const uint4*)g_Wt;
        #pragma unroll
        for (int it = 0; it < 8; it++){
            int idx = tid + it*256;
            int o = idx >> 5, kq = idx & 31;
            *(uint4*)&Wsh[o*AS + kq*8] = Wt4[idx];
        }
    }
    if (tid < 128)
        ((float4*)sshf)[tid] = ((const float4*)g_p)[b*Nn + i0 + tid];
    __syncthreads();

    int lane = tid & 31, wid = tid >> 5;
    int wr = wid >> 1, wc = wid & 1;
    int gid = lane >> 2, tg = lane & 3;

    float2 vc[8];
    float4 pjv;
    float  addv;
    {
        int j = jp*JPB;
        size_t base_c = (((size_t)(b*Nn) + i0)*Nn + j)*Cc;
        #pragma unroll
        for (int it = 0; it < 8; it++){
            int idx = tid + it*256;
            int i = idx >> 4, cp = idx & 15;
            vc[it] = *(const float2*)(x + base_c + (size_t)i*(Nn*Cc) + cp*2);
        }
        pjv  = ((const float4*)g_p)[b*Nn + j];
        addv = g_add[(b*Nn + j)*OUTn + (tid & 63)];
    }

    for (int jj = 0; jj < JPB; jj++){
        int j = jp*JPB + jj;
        if (jj > 0) __syncthreads();

        {
            size_t base_r = (((size_t)(b*Nn) + j)*Nn + i0)*Cc;
            #pragma unroll
            for (int it = 0; it < 8; it++){
                int idx = tid + it*256;
                int i = idx >> 4, cp = idx & 15;
                float4 pi = ((const float4*)sshf)[i];
                float4 s = make_float4(pi.x*pjv.x, pi.y*pjv.y, pi.z*pjv.z, pi.w*pjv.w);
                float2 v = vc[it];
                __half* arow = Ash + i*AS + cp*2;
                *(half2*)(arow     ) = __floats2half2_rn(s.x*v.x, s.x*v.y);
                *(half2*)(arow + 32) = __floats2half2_rn(s.y*v.x, s.y*v.y);
                *(half2*)(arow + 64) = __floats2half2_rn(s.z*v.x, s.z*v.y);
                *(half2*)(arow + 96) = __floats2half2_rn(s.w*v.x, s.w*v.y);
                float2 w = *(const float2*)(x + base_r + (size_t)i*Cc + cp*2);
                __half* brow = arow + 128;
                *(half2*)(brow     ) = __floats2half2_rn(s.x*w.x, s.x*w.y);
                *(half2*)(brow + 32) = __floats2half2_rn(s.y*w.x, s.y*w.y);
                *(half2*)(brow + 64) = __floats2half2_rn(s.z*w.x, s.z*w.y);
                *(half2*)(brow + 96) = __floats2half2_rn(s.w*w.x, s.w*w.y);
            }
            if (tid < 64) addsh[tid] = addv;
        }
        __syncthreads();

        if (jj + 1 < JPB){
            int j2 = j + 1;
            size_t base_c = (((size_t)(b*Nn) + i0)*Nn + j2)*Cc;
            #pragma unroll
            for (int it = 0; it < 8; it++){
                int idx = tid + it*256;
                int i = idx >> 4, cp = idx & 15;
                vc[it] = *(const float2*)(x + base_c + (size_t)i*(Nn*Cc) + cp*2);
            }
            pjv  = ((const float4*)g_p)[b*Nn + j2];
            addv = g_add[(b*Nn + j2)*OUTn + (tid & 63)];
        }

        float acc[2][4][4];
        #pragma unroll
        for (int rt = 0; rt < 2; rt++)
            #pragma unroll
            for (int nt = 0; nt < 4; nt++)
                #pragma unroll
                for (int q = 0; q < 4; q++) acc[rt][nt][q] = 0.f;

        #pragma unroll
        for (int kk = 0; kk < 16; kk++){
            int k0 = kk*16;
            uint32_t a[2][4];
            #pragma unroll
            for (int rt = 0; rt < 2; rt++){
                int r = wr*32 + rt*16 + gid;
                const __half* ap = Ash + r*AS + k0 + tg*2;
                a[rt][0] = *(const uint32_t*)(ap);
                a[rt][1] = *(const uint32_t*)(ap + 8*AS);
                a[rt][2] = *(const uint32_t*)(ap + 8);
                a[rt][3] = *(const uint32_t*)(ap + 8*AS + 8);
            }
            #pragma unroll
            for (int nt = 0; nt < 4; nt++){
                int o = wc*32 + nt*8 + gid;
                const __half* bp = Wsh + o*AS + k0 + tg*2;
                uint32_t b0 = *(const uint32_t*)(bp);
                uint32_t b1 = *(const uint32_t*)(bp + 8);
                mma16816(acc[0][nt], a[0], b0, b1);
                mma16816(acc[1][nt], a[1], b0, b1);
            }
        }

        #pragma unroll
        for (int rt = 0; rt < 2; rt++){
            int r = i0 + wr*32 + rt*16 + gid;
            #pragma unroll
            for (int nt = 0; nt < 4; nt++){
                int o = wc*32 + nt*8 + tg*2;
                float2 ad = *(const float2*)&addsh[o];
                size_t base = (((size_t)(b*Nn) + r)*Nn + j)*OUTn + o;
                float2 v0 = make_float2(acc[rt][nt][0] + ad.x, acc[rt][nt][1] + ad.y);
                float2 v1 = make_float2(acc[rt][nt][2] + ad.x, acc[rt][nt][3] + ad.y);
                *(float2*)(out + base) = v0;
                *(float2*)(out + base + (size_t)8*Nn*OUTn) = v1;
            }
        }
    }
}

// ---------------- launch ----------------
extern "C" void kernel_launch(void* const* d_in, const int* in_sizes, int n_in,
                              void* d_out, int out_size) {
    const float* x    = (const float*)d_in[0];
    const float* w1nb = (const float*)d_in[1];
    const float* b1nb = (const float*)d_in[2];
    const float* w0nb = (const float*)d_in[3];
    const float* b0nb = (const float*)d_in[4];
    const float* w2d  = (const float*)d_in[5];
    const float* b2d  = (const float*)d_in[6];
    const float* w1d  = (const float*)d_in[7];
    const float* b1d  = (const float*)d_in[8];
    const float* w0d  = (const float*)d_in[9];
    const float* b0d  = (const float*)d_in[10];
    float* out = (float*)d_out;

    cudaFuncSetAttribute(k_main, cudaFuncAttributeMaxDynamicSharedMemorySize, SMEM_MAIN);
    cudaFuncSetAttribute(k_add, cudaFuncAttributeMaxDynamicSharedMemorySize, ADD_SMEM);

    k_sweep1<<<Bn*32 + 64, 256>>>(x, w2d);
    k_neighb<<<Bn, 1024>>>(x, w1nb, b1nb, w0nb, b0nb);
    k_sweep2<<<2*Bn*Nn, 256>>>(x);
    k_add<<<Bn*64, 256, ADD_SMEM>>>(w1d, w0d, b0d, b1d, b2d);
    k_main<<<Bn*Nn*2/JPB, 256, SMEM_MAIN>>>(x, out);
}

// round 11
// speedup vs baseline: 1.3907x; 1.3907x over previous
#include <cuda_runtime.h>
#include <cuda_fp16.h>
#include <cstdint>

#define Bn 4
#define Nn 256
#define Cc 32
#define Mm 4
#define OUTn 64

// ---------------- scratch (device globals: no allocation allowed) ----------------
__device__ float g_S1[Bn*Nn*Cc];      // rowsum  (mean over axis1): S1[b,t,c] = (1/n) sum_i x[b,i,t,c]
__device__ float g_S2[Bn*Nn*Cc];      // colsum  (mean over axis2): S2[b,t,c] = (1/n) sum_j x[b,t,j,c]
__device__ float g_D [Bn*Nn*Cc];      // diag:   D[b,t,c] = x[b,t,t,c]
__device__ float g_p [Bn*Nn*Mm];      // sigmoid neighborhood
__device__ float g_U [Bn*Nn*Mm*Cc];   // U[b,t,m,c] = (1/n) sum_i p[i,m] x[b,i,t,c]
__device__ float g_V [Bn*Nn*Mm*Cc];   // V[b,t,m,c] = (1/n) sum_j p[j,m] x[b,t,j,c]
__device__ float g_part1[Bn*16*128];  // rcs2 partials (16 t-slices per b)
__device__ float g_part2[Bn*16*128];  // ds2  partials
__device__ float g_add[Bn*Nn*OUTn];   // per (b, j, o) additive term
__device__ __half g_Wt[OUTn*2*Mm*Cc]; // w2d transposed: Wt[o][k], k = 0..255

// ---------------- sweep 1: rowpass (S2, D) + colpass (S1) + w2d->half, one launch ----------------
__global__ void k_sweep1(const float* __restrict__ x, const float* __restrict__ w2d){
    int blk = blockIdx.x;
    int tid = threadIdx.x;
    if (blk >= 2*Bn*Nn){
        int idx = (blk - 2*Bn*Nn) * 256 + tid;   // 16384
        int o = idx >> 8, k = idx & 255;
        g_Wt[idx] = __float2half(w2d[k*OUTn + o]);
        return;
    }
    __shared__ float red[8][32];
    int c = tid & 31, g = tid >> 5;
    if (blk < Bn*Nn){
        int bt = blk;
        int t = bt & (Nn-1);
        const float* xrow = x + (size_t)bt * Nn * Cc;
        float s = 0.f;
        #pragma unroll 8
        for (int j = g; j < Nn; j += 8) s += xrow[j*Cc + c];
        red[g][c] = s;
        __syncthreads();
        if (g == 0){
            float tot = 0.f;
            #pragma unroll
            for (int k = 0; k < 8; k++) tot += red[k][c];
            g_S2[bt*Cc + c] = tot * (1.0f/Nn);
            g_D [bt*Cc + c] = xrow[t*Cc + c];
        }
    } else {
        int bt = blk - Bn*Nn;
        int b = bt >> 8, t = bt & (Nn-1);
        const float* xb = x + (size_t)b*Nn*Nn*Cc + (size_t)t*Cc;
        float s = 0.f;
        #pragma unroll 8
        for (int i = g; i < Nn; i += 8) s += xb[(size_t)i*Nn*Cc + c];
        red[g][c] = s;
        __syncthreads();
        if (g == 0){
            float tot = 0.f;
            #pragma unroll
            for (int k = 0; k < 8; k++) tot += red[k][c];
            g_S1[bt*Cc + c] = tot * (1.0f/Nn);
        }
    }
}

// ---------------- neighborhood sigmoid: p[b,t,m], 1024 threads ----------------
__global__ __launch_bounds__(1024) void k_neighb(const float* __restrict__ w1, const float* __restrict__ b1,
                         const float* __restrict__ w0, const float* __restrict__ b0){
    int b = blockIdx.x;
    __shared__ float w1s[3*Cc*Mm];   // 384
    __shared__ float w0s[2*Cc*Mm];   // 256
    __shared__ float rcs[Cc], ds[Cc], z0[Mm];
    __shared__ float r1[32][32], r2[32][32];
    int tid = threadIdx.x;
    if (tid < 3*Cc*Mm) w1s[tid] = w1[tid];
    if (tid < 2*Cc*Mm) w0s[tid] = w0[tid];
    int c = tid & 31, g = tid >> 5;     // 32 groups
    float s1 = 0.f, s2 = 0.f;
    #pragma unroll
    for (int t = g; t < Nn; t += 32){
        s1 += g_S1[(b*Nn + t)*Cc + c];
        s2 += g_D [(b*Nn + t)*Cc + c];
    }
    r1[g][c] = s1; r2[g][c] = s2;
    __syncthreads();
    if (tid < 32){
        float a = 0.f, d = 0.f;
        #pragma unroll
        for (int k = 0; k < 32; k++){ a += r1[k][c]; d += r2[k][c]; }
        rcs[c] = a * (1.0f/Nn);
        ds[c]  = d * (1.0f/Nn);
    }
    __syncthreads();
    if (tid < Mm){
        int m = tid;
        float z = b0[m];
        #pragma unroll
        for (int cc = 0; cc < Cc; cc++)
            z += rcs[cc]*w0s[cc*Mm + m] + ds[cc]*w0s[(Cc+cc)*Mm + m];
        z0[m] = z;
    }
    __syncthreads();
    int t = tid >> 2, m = tid & 3;
    const float* S1r = &g_S1[(b*Nn + t)*Cc];
    const float* S2r = &g_S2[(b*Nn + t)*Cc];
    const float* Dr  = &g_D [(b*Nn + t)*Cc];
    float node = b1[m] + z0[m];
    #pragma unroll
    for (int cc = 0; cc < Cc; cc++)
        node += S1r[cc]*w1s[cc*Mm+m] + S2r[cc]*w1s[(Cc+cc)*Mm+m] + Dr[cc]*w1s[(2*Cc+cc)*Mm+m];
    g_p[(b*Nn + t)*Mm + m] = 1.0f / (1.0f + expf(-node));
}

// ---------------- sweep 2: p-weighted contractions (V and U) in one launch ----------------
__global__ void k_sweep2(const float* __restrict__ x){
    int blk = blockIdx.x;
    bool is_v = blk < Bn*Nn;
    int bt = is_v ? blk : blk - Bn*Nn;
    int b = bt >> 8, t = bt & (Nn-1);
    const float* base;
    size_t stride;
    if (is_v){ base = x + (size_t)bt * Nn * Cc;                     stride = Cc; }
    else     { base = x + (size_t)b*Nn*Nn*Cc + (size_t)t*Cc;        stride = (size_t)Nn*Cc; }
    __shared__ float pv[Nn*Mm];
    __shared__ float red[8*Mm*32];
    int tid = threadIdx.x;
    ((float4*)pv)[tid] = ((const float4*)g_p)[b*Nn + tid];   // 256 float4 = 1024 floats
    __syncthreads();
    int c = tid & 31, g = tid >> 5;
    float acc[Mm] = {0.f,0.f,0.f,0.f};
    #pragma unroll 8
    for (int j = g; j < Nn; j += 8){
        float v = base[(size_t)j*stride + c];
        #pragma unroll
        for (int m = 0; m < Mm; m++) acc[m] += v * pv[j*Mm + m];
    }
    #pragma unroll
    for (int m = 0; m < Mm; m++) red[(g*Mm + m)*32 + c] = acc[m];
    __syncthreads();
    if (g < Mm){
        int m = g;
        float s = 0.f;
        #pragma unroll
        for (int k = 0; k < 8; k++) s += red[(k*Mm + m)*32 + c];
        float* dst = is_v ? g_V : g_U;
        dst[(bt*Mm + m)*Cc + c] = s * (1.0f/Nn);
    }
}

// ---------------- rcs2/ds2 partials: grid = Bn*16, 8 t per thread ----------------
__global__ void k_rcs2p(){
    int blk = blockIdx.x;
    int b = blk >> 4, slice = blk & 15;
    __shared__ float pr1[256], pr2[256];
    int tid = threadIdx.x;
    int mc = tid & 127, sub = tid >> 7;
    int m = mc >> 5, c = mc & 31;
    float s1 = 0.f, s2 = 0.f;
    int t0 = slice*16 + sub*8;
    #pragma unroll
    for (int t = t0; t < t0+8; t++){
        float pvv = g_p[(b*Nn + t)*Mm + m];
        s1 += pvv * g_V[((b*Nn + t)*Mm + m)*Cc + c];
        s2 += pvv * pvv * g_D[(b*Nn + t)*Cc + c];
    }
    pr1[tid] = s1; pr2[tid] = s2;
    __syncthreads();
    if (tid < 128){
        g_part1[(b*16 + slice)*128 + tid] = pr1[tid] + pr1[tid+128];
        g_part2[(b*16 + slice)*128 + tid] = pr2[tid] + pr2[tid+128];
    }
}

// ---------------- add[b,t,o]: 256 blocks, 4 t per block, thread = one (t,o) ----------------
#define ADD_SMEM (4*384*4 + 96*64*4)
__global__ void k_add(const float* __restrict__ w1d, const float* __restrict__ w0d,
                      const float* __restrict__ b0d, const float* __restrict__ b1d,
                      const float* __restrict__ b2d){
    extern __shared__ float ash[];
    float* o1  = ash;            // [4][384]
    float* wsh = ash + 4*384;    // [96][64] chunk of w1d
    __shared__ float rsh[128], dsh[128], zred[256], z0sh[64];
    int b = blockIdx.x >> 6;
    int t0 = (blockIdx.x & 63) * 4;
    int tid = threadIdx.x;

    // fill o1 for 4 t's: 1536 elements
    #pragma unroll
    for (int it = 0; it < 6; it++){
        int idx = tid + it*256;
        int tl = idx / 384, k = idx - tl*384;
        int t = t0 + tl;
        int seg = k >> 7, mc = k & 127;
        int m = mc >> 5, c = mc & 31;
        float pv = g_p[(b*Nn + t)*Mm + m];
        float val;
        if (seg == 0)      val = pv * g_U[((b*Nn + t)*Mm + m)*Cc + c];
        else if (seg == 1) val = pv * g_V[((b*Nn + t)*Mm + m)*Cc + c];
        else               val = pv * pv * g_D[(b*Nn + t)*Cc + c];
        o1[idx] = val;
    }
    // z0 prologue from partials (16 slices)
    if (tid < 128){
        float a = 0.f, d = 0.f;
        #pragma unroll
        for (int s = 0; s < 16; s++){
            a += g_part1[(b*16 + s)*128 + tid];
            d += g_part2[(b*16 + s)*128 + tid];
        }
        rsh[tid] = a * (1.0f/Nn);
        dsh[tid] = d * (1.0f/Nn);
    }
    __syncthreads();
    {
        int o = tid & 63, q = tid >> 6;
        float s = 0.f;
        int k0 = q*32;
        #pragma unroll
        for (int k = k0; k < k0+32; k++)
            s += rsh[k]*w0d[k*OUTn + o] + dsh[k]*w0d[(128+k)*OUTn + o];
        zred[tid] = s;
    }
    __syncthreads();
    if (tid < 64)
        z0sh[tid] = zred[tid] + zred[tid+64] + zred[tid+128] + zred[tid+192]
                  + b0d[tid] + b1d[tid] + b2d[tid];

    int tq = tid >> 6, o = tid & 63;
    float acc = 0.f;
    #pragma unroll
    for (int chunk = 0; chunk < 4; chunk++){
        __syncthreads();
        {   // stage 96 rows of w1d: 1536 float4
            const float4* w4 = (const float4*)(w1d + chunk*96*64);
            #pragma unroll
            for (int it = 0; it < 6; it++)
                ((float4*)wsh)[tid + it*256] = w4[tid + it*256];
        }
        __syncthreads();
        #pragma unroll 8
        for (int k = 0; k < 96; k++)
            acc += o1[tq*384 + chunk*96 + k] * wsh[k*64 + o];
    }
    g_add[(b*Nn + t0 + tq)*OUTn + o] = acc + z0sh[o];
}

// ---------------- main fused GEMM: JPB 4, column-tile register prefetch ----------------
__device__ __forceinline__ void mma16816(float* c, const uint32_t* a, uint32_t b0, uint32_t b1){
    asm volatile("mma.sync.aligned.m16n8k16.row.col.f32.f16.f16.f32 "
        "{%0,%1,%2,%3}, {%4,%5,%6,%7}, {%8,%9}, {%0,%1,%2,%3};\n"
        : "+f"(c[0]), "+f"(c[1]), "+f"(c[2]), "+f"(c[3])
        : "r"(a[0]), "r"(a[1]), "r"(a[2]), "r"(a[3]), "r"(b0), "r"(b1));
}

#define AS 264   // padded row stride (halves) for A and W tiles
#define SMEM_MAIN (128*AS*2 + 64*AS*2 + 512*4 + 64*4)
#define JPB 4    // grid = 512 blocks

__global__ __launch_bounds__(256, 2) void k_main(const float* __restrict__ x, float* __restrict__ out){
    extern __shared__ __align__(16) char smem[];
    __half* Ash  = (__half*)smem;                 // [128][AS]
    __half* Wsh  = Ash + 128*AS;                  // [64][AS]
    float*  sshf = (float*)(Wsh + 64*AS);         // [128][4] pi factors (per block, j-independent)
    float*  addsh = sshf + 512;                   // [64]

    int blk = blockIdx.x;
    int ib = blk & 1, jp = (blk >> 1) & 63, b = blk >> 7;
    int i0 = ib * 128;
    int tid = threadIdx.x;

    // W tile: 64 rows x 256 halves = 2048 uint4, loaded once for JPB j's
    {
        const uint4* Wt4 = (const uint4*)g_Wt;
        #pragma unroll
        for (int it = 0; it < 8; it++){
            int idx = tid + it*256;               // < 2048
            int o = idx >> 5, kq = idx & 31;
            *(uint4*)&Wsh[o*AS + kq*8] = Wt4[idx];
        }
    }
    // pi factors once per block (j-independent)
    if (tid < 128)
        ((float4*)sshf)[tid] = ((const float4*)g_p)[b*Nn + i0 + tid];
    __syncthreads();

    int lane = tid & 31, wid = tid >> 5;
    int wr = wid >> 1, wc = wid & 1;              // 4 row-tiles x 2 col-tiles of warps
    int gid = lane >> 2, tg = lane & 3;

    // register prefetch: column tile only (the strided/slow one)
    float2 vc[8];
    float4 pjv;
    float  addv;
    {
        int j = jp*JPB;
        size_t base_c = (((size_t)(b*Nn) + i0)*Nn + j)*Cc;
        #pragma unroll
        for (int it = 0; it < 8; it++){
            int idx = tid + it*256;
            int i = idx >> 4, cp = idx & 15;
            vc[it] = *(const float2*)(x + base_c + (size_t)i*(Nn*Cc) + cp*2);
        }
        pjv  = ((const float4*)g_p)[b*Nn + j];
        addv = g_add[(b*Nn + j)*OUTn + (tid & 63)];
    }

    for (int jj = 0; jj < JPB; jj++){
        int j = jp*JPB + jj;
        if (jj > 0) __syncthreads();              // MMA/epilogue of prev j done with Ash/addsh

        // A build: column half from prefetched regs, row half live-loaded (contiguous)
        {
            size_t base_r = (((size_t)(b*Nn) + j)*Nn + i0)*Cc;
            #pragma unroll
            for (int it = 0; it < 8; it++){
                int idx = tid + it*256;               // < 2048
                int i = idx >> 4, cp = idx & 15;
                float4 pi = ((const float4*)sshf)[i];
                float4 s = make_float4(pi.x*pjv.x, pi.y*pjv.y, pi.z*pjv.z, pi.w*pjv.w);
                float2 v = vc[it];
                __half* arow = Ash + i*AS + cp*2;
                *(half2*)(arow     ) = __floats2half2_rn(s.x*v.x, s.x*v.y);
                *(half2*)(arow + 32) = __floats2half2_rn(s.y*v.x, s.y*v.y);
                *(half2*)(arow + 64) = __floats2half2_rn(s.z*v.x, s.z*v.y);
                *(half2*)(arow + 96) = __floats2half2_rn(s.w*v.x, s.w*v.y);
                float2 w = *(const float2*)(x + base_r + (size_t)i*Cc + cp*2);
                __half* brow = arow + 128;
                *(half2*)(brow     ) = __floats2half2_rn(s.x*w.x, s.x*w.y);
                *(half2*)(brow + 32) = __floats2half2_rn(s.y*w.x, s.y*w.y);
                *(half2*)(brow + 64) = __floats2half2_rn(s.z*w.x, s.z*w.y);
                *(half2*)(brow + 96) = __floats2half2_rn(s.w*w.x, s.w*w.y);
            }
            if (tid < 64) addsh[tid] = addv;
        }
        __syncthreads();

        // prefetch next j's column tile while MMA runs
        if (jj + 1 < JPB){
            int j2 = j + 1;
            size_t base_c = (((size_t)(b*Nn) + i0)*Nn + j2)*Cc;
            #pragma unroll
            for (int it = 0; it < 8; it++){
                int idx = tid + it*256;
                int i = idx >> 4, cp = idx & 15;
                vc[it] = *(const float2*)(x + base_c + (size_t)i*(Nn*Cc) + cp*2);
            }
            pjv  = ((const float4*)g_p)[b*Nn + j2];
            addv = g_add[(b*Nn + j2)*OUTn + (tid & 63)];
        }

        float acc[2][4][4];
        #pragma unroll
        for (int rt = 0; rt < 2; rt++)
            #pragma unroll
            for (int nt = 0; nt < 4; nt++)
                #pragma unroll
                for (int q = 0; q < 4; q++) acc[rt][nt][q] = 0.f;

        #pragma unroll
        for (int kk = 0; kk < 16; kk++){
            int k0 = kk*16;
            uint32_t a[2][4];
            #pragma unroll
            for (int rt = 0; rt < 2; rt++){
                int r = wr*32 + rt*16 + gid;
                const __half* ap = Ash + r*AS + k0 + tg*2;
                a[rt][0] = *(const uint32_t*)(ap);
                a[rt][1] = *(const uint32_t*)(ap + 8*AS);
                a[rt][2] = *(const uint32_t*)(ap + 8);
                a[rt][3] = *(const uint32_t*)(ap + 8*AS + 8);
            }
            #pragma unroll
            for (int nt = 0; nt < 4; nt++){
                int o = wc*32 + nt*8 + gid;
                const __half* bp = Wsh + o*AS + k0 + tg*2;
                uint32_t b0 = *(const uint32_t*)(bp);
                uint32_t b1 = *(const uint32_t*)(bp + 8);
                mma16816(acc[0][nt], a[0], b0, b1);
                mma16816(acc[1][nt], a[1], b0, b1);
            }
        }

        #pragma unroll
        for (int rt = 0; rt < 2; rt++){
            int r = i0 + wr*32 + rt*16 + gid;
            #pragma unroll
            for (int nt = 0; nt < 4; nt++){
                int o = wc*32 + nt*8 + tg*2;
                float2 ad = *(const float2*)&addsh[o];
                size_t base = (((size_t)(b*Nn) + r)*Nn + j)*OUTn + o;
                float2 v0 = make_float2(acc[rt][nt][0] + ad.x, acc[rt][nt][1] + ad.y);
                float2 v1 = make_float2(acc[rt][nt][2] + ad.x, acc[rt][nt][3] + ad.y);
                *(float2*)(out + base) = v0;
                *(float2*)(out + base + (size_t)8*Nn*OUTn) = v1;
            }
        }
    }
}

// ---------------- launch ----------------
extern "C" void kernel_launch(void* const* d_in, const int* in_sizes, int n_in,
                              void* d_out, int out_size) {
    const float* x    = (const float*)d_in[0];
    const float* w1nb = (const float*)d_in[1];
    const float* b1nb = (const float*)d_in[2];
    const float* w0nb = (const float*)d_in[3];
    const float* b0nb = (const float*)d_in[4];
    const float* w2d  = (const float*)d_in[5];
    const float* b2d  = (const float*)d_in[6];
    const float* w1d  = (const float*)d_in[7];
    const float* b1d  = (const float*)d_in[8];
    const float* w0d  = (const float*)d_in[9];
    const float* b0d  = (const float*)d_in[10];
    float* out = (float*)d_out;

    cudaFuncSetAttribute(k_main, cudaFuncAttributeMaxDynamicSharedMemorySize, SMEM_MAIN);
    cudaFuncSetAttribute(k_add, cudaFuncAttributeMaxDynamicSharedMemorySize, ADD_SMEM);

    k_sweep1<<<2*Bn*Nn + 64, 256>>>(x, w2d);
    k_neighb<<<Bn, 1024>>>(w1nb, b1nb, w0nb, b0nb);
    k_sweep2<<<2*Bn*Nn, 256>>>(x);
    k_rcs2p<<<Bn*16, 256>>>();
    k_add<<<Bn*64, 256, ADD_SMEM>>>(w1d, w0d, b0d, b1d, b2d);
    k_main<<<Bn*Nn*2/JPB, 256, SMEM_MAIN>>>(x, out);
}